// round 2
// baseline (speedup 1.0000x reference)
#include <cuda_runtime.h>
#include <math.h>

#define VV 20000
#define HH 512
#define BB 128
#define SS 64
#define TD 32
#define NB 128

// ---------------- scratch (device globals) ----------------
__device__ float g_xg[BB * SS * 2048];
__device__ float g_enc_out[BB * SS * HH];
__device__ float g_keys[BB * SS * HH];
__device__ float g_embW[TD * BB * 2048];
__device__ float g_hs[TD * BB * HH];
__device__ float g_hbuf[2 * HH * BB];     // [2][k=512][b=128]
__device__ float g_cst[HH * BB];          // [hid][b]
__device__ float g_q[HH * BB];            // [qrow][b]
__device__ float g_ctx[HH * BB];          // [k][b]
__device__ int   g_rows[TD * BB];
__device__ unsigned g_bar_enc;
__device__ unsigned g_bar_dec;

__device__ __forceinline__ float sigf(float x) { return 1.f / (1.f + __expf(-x)); }
__device__ __forceinline__ float tanha(float x) {
    float y; asm("tanh.approx.f32 %0, %1;" : "=f"(y) : "f"(x)); return y;
}

// grid barrier (all NB blocks resident; monotonic counter, reset per launch)
__device__ __forceinline__ void gbar(unsigned* ctr, unsigned target) {
    __syncthreads();
    if (threadIdx.x == 0) {
        __threadfence();
        atomicAdd(ctr, 1u);
        while (*(volatile unsigned*)ctr < target) __nanosleep(64);
        __threadfence();
    }
    __syncthreads();
}

// stage helpers: 32 k-rows x 128 b, smem row stride 132
__device__ __forceinline__ void prefetch4(float4* pre, const float* src) {
    const int tid = threadIdx.x;
#pragma unroll
    for (int i = 0; i < 4; i++) {
        int j = i * 256 + tid;
        pre[i] = __ldcg((const float4*)(src + ((j >> 5) << 7) + ((j & 31) << 2)));
    }
}
__device__ __forceinline__ void commit4(float* st, const float4* pre) {
    const int tid = threadIdx.x;
#pragma unroll
    for (int i = 0; i < 4; i++) {
        int j = i * 256 + tid;
        *(float4*)(st + (j >> 5) * 132 + ((j & 31) << 2)) = pre[i];
    }
}

// ---------------- persistent encoder ----------------
// block i owns hidden units 4i..4i+3 (16 gate rows), all 128 batches.
__global__ void __launch_bounds__(256, 1) enc_persist(const float* __restrict__ Whh)
{
    extern __shared__ float sm[];
    float* ws    = sm;              // 16*513
    float* stage = ws + 8208;       // 2*32*132
    float* gbufS = stage + 8448;    // 16*132
    float* csm   = gbufS + 2112;    // 512

    const int tid = threadIdx.x;
    const int blk = blockIdx.x;

    for (int i = tid; i < 16 * 512; i += 256) {
        int r = i >> 9, k = i & 511;
        int g = r >> 2, u = r & 3;
        ws[r * 513 + k] = Whh[(size_t)(g * 512 + blk * 4 + u) * 512 + k];
    }
    if (tid < 256) { csm[tid] = 0.f; csm[tid + 256] = 0.f; }
    __syncthreads();

    const int r  = tid >> 4;     // 0..15 gate row
    const int b8 = tid & 15;     // batch group of 8

    for (int t = 0; t < SS; t++) {
        const float* hsrc = g_hbuf + (t & 1) * 65536;

        // prefetch xg for the cell phase (hide L2 latency behind k-loop)
        float xr[2][4];
#pragma unroll
        for (int ci = 0; ci < 2; ci++) {
            int idx = tid + ci * 256;
            int u = idx >> 7, b = idx & 127;
            const size_t base = ((size_t)b * SS + t) * 2048 + blk * 4 + u;
            xr[ci][0] = __ldg(&g_xg[base]);
            xr[ci][1] = __ldg(&g_xg[base + 512]);
            xr[ci][2] = __ldg(&g_xg[base + 1024]);
            xr[ci][3] = __ldg(&g_xg[base + 1536]);
        }

        float4 pre[4];
        prefetch4(pre, hsrc);
        commit4(stage, pre);
        __syncthreads();

        float a0 = 0.f, a1 = 0.f, a2 = 0.f, a3 = 0.f, a4 = 0.f, a5 = 0.f, a6 = 0.f, a7 = 0.f;
        for (int c = 0; c < 16; c++) {
            float* st = stage + (c & 1) * 4224;
            if (c < 15) prefetch4(pre, hsrc + (c + 1) * 4096);
            const float* wrow = ws + r * 513 + c * 32;
#pragma unroll
            for (int kk = 0; kk < 32; kk++) {
                float w = wrow[kk];
                const float* hp = st + kk * 132 + (b8 << 3);
                float4 h0 = *(const float4*)hp;
                float4 h1 = *(const float4*)(hp + 4);
                a0 += w * h0.x; a1 += w * h0.y; a2 += w * h0.z; a3 += w * h0.w;
                a4 += w * h1.x; a5 += w * h1.y; a6 += w * h1.z; a7 += w * h1.w;
            }
            __syncthreads();
            if (c < 15) commit4(stage + ((c + 1) & 1) * 4224, pre);
            __syncthreads();
        }
        {
            float* gr = gbufS + r * 132 + (b8 << 3);
            gr[0] = a0; gr[1] = a1; gr[2] = a2; gr[3] = a3;
            gr[4] = a4; gr[5] = a5; gr[6] = a6; gr[7] = a7;
        }
        __syncthreads();
#pragma unroll
        for (int ci = 0; ci < 2; ci++) {
            int idx = tid + ci * 256;
            int u = idx >> 7, b = idx & 127;
            float ig = gbufS[u * 132 + b]        + xr[ci][0];
            float fg = gbufS[(4 + u) * 132 + b]  + xr[ci][1];
            float gg = gbufS[(8 + u) * 132 + b]  + xr[ci][2];
            float og = gbufS[(12 + u) * 132 + b] + xr[ci][3];
            float cp = csm[u * 128 + b];
            float cn = sigf(fg) * cp + sigf(ig) * tanhf(gg);
            float hn = sigf(og) * tanhf(cn);
            csm[u * 128 + b] = cn;
            int hr = blk * 4 + u;
            __stcg(&g_hbuf[((t + 1) & 1) * 65536 + hr * 128 + b], hn);
            g_enc_out[((size_t)b * SS + t) * 512 + hr] = hn;
            if (t == SS - 1) g_cst[hr * 128 + b] = cn;
        }
        gbar(&g_bar_enc, (unsigned)(t + 1) * NB);
    }
}

// ---------------- persistent decoder ----------------
__global__ void __launch_bounds__(256, 1) dec_persist(
    const float* __restrict__ Wq, const float* __restrict__ bq,
    const float* __restrict__ v_w, const float* __restrict__ v_b,
    const int* __restrict__ src,
    const float* __restrict__ dWih, const float* __restrict__ dWhh,
    float* __restrict__ attn_out, int writeAttn)
{
    extern __shared__ float sm[];
    float* wsC   = sm;              // 16*1025 = 16400
    float* wq    = wsC + 16400;     // 4*513  = 2052
    float* stage = wq + 2052;       // 8448
    float* gbufS = stage + 8448;    // 2112
    float* qred  = gbufS + 2112;    // 4*516 = 2064
    float* csm   = qred + 2064;     // 512
    float* qs    = csm + 512;       // 512
    float* vs    = qs + 512;        // 512
    float* scs   = vs + 512;        // 64
    float* wsf   = scs + 64;        // 64

    const int tid = threadIdx.x;
    const int blk = blockIdx.x;

    for (int i = tid; i < 16 * 1024; i += 256) {
        int r = i >> 10, k = i & 1023;
        int g = r >> 2, u = r & 3;
        int grow = g * 512 + blk * 4 + u;
        float w = (k < 512) ? dWih[(size_t)grow * 768 + 256 + k]
                            : dWhh[(size_t)grow * 512 + (k - 512)];
        wsC[r * 1025 + k] = w;
    }
    for (int i = tid; i < 4 * 512; i += 256) {
        int r = i >> 9, k = i & 511;
        wq[r * 513 + k] = Wq[(size_t)(blk * 4 + r) * 512 + k];
    }
    for (int i = tid; i < 512; i += 256) vs[i] = v_w[i];
    if (tid < 256) {
        csm[tid]       = g_cst[blk * 512 + tid];
        csm[tid + 256] = g_cst[blk * 512 + tid + 256];
    }
    const float vb = v_b[0];
    __syncthreads();

    const int r16 = tid >> 4, b8 = tid & 15;          // phase C slot
    const int kwy = tid >> 6, rA = (tid >> 4) & 3;    // phase A slot

    for (int t = 0; t < TD; t++) {
        const float* hsrc = g_hbuf + (t & 1) * 65536;
        float4 pre[4];

        // ---- phase A: q = h @ Wq^T + bq (4 rows per block, split-k 4) ----
        float q0 = 0.f, q1 = 0.f, q2 = 0.f, q3 = 0.f, q4 = 0.f, q5 = 0.f, q6 = 0.f, q7 = 0.f;
        prefetch4(pre, hsrc);
        commit4(stage, pre);
        __syncthreads();
        for (int c = 0; c < 16; c++) {
            float* st = stage + (c & 1) * 4224;
            if (c < 15) prefetch4(pre, hsrc + (c + 1) * 4096);
            const float* wrow = wq + rA * 513 + c * 32 + kwy * 8;
            const float* stk = st + (kwy * 8) * 132 + (b8 << 3);
#pragma unroll
            for (int kk = 0; kk < 8; kk++) {
                float w = wrow[kk];
                const float* hp = stk + kk * 132;
                float4 h0 = *(const float4*)hp;
                float4 h1 = *(const float4*)(hp + 4);
                q0 += w * h0.x; q1 += w * h0.y; q2 += w * h0.z; q3 += w * h0.w;
                q4 += w * h1.x; q5 += w * h1.y; q6 += w * h1.z; q7 += w * h1.w;
            }
            __syncthreads();
            if (c < 15) commit4(stage + ((c + 1) & 1) * 4224, pre);
            __syncthreads();
        }
        {
            float* qr = qred + kwy * 516 + rA * 128 + (b8 << 3);
            qr[0] = q0; qr[1] = q1; qr[2] = q2; qr[3] = q3;
            qr[4] = q4; qr[5] = q5; qr[6] = q6; qr[7] = q7;
        }
        __syncthreads();
        for (int i = tid; i < 512; i += 256) {
            int rr = i >> 7;
            float v = qred[i] + qred[516 + i] + qred[1032 + i] + qred[1548 + i] + bq[blk * 4 + rr];
            __stcg(&g_q[(blk * 4 + rr) * 128 + (i & 127)], v);
        }
        gbar(&g_bar_dec, (unsigned)(t * 3 + 1) * NB);

        // ---- phase B: scores + softmax + ctx for batch b = blk ----
        {
            const int b = blk;
            for (int i = tid; i < 512; i += 256) qs[i] = __ldcg(&g_q[i * 128 + b]);
            __syncthreads();
            const int warp = tid >> 5, lane = tid & 31;
            for (int s = warp; s < SS; s += 8) {
                const float* kp = g_keys + ((size_t)b * SS + s) * 512;
                float sum = 0.f;
#pragma unroll 4
                for (int j = lane; j < 512; j += 32)
                    sum += tanha(qs[j] + kp[j]) * vs[j];
#pragma unroll
                for (int o = 16; o; o >>= 1) sum += __shfl_xor_sync(0xffffffffu, sum, o);
                if (lane == 0) {
                    sum += vb;
                    if (src[b * SS + s] == 0) sum = -1e9f;
                    scs[s] = sum;
                }
            }
            __syncthreads();
            if (warp == 0) {
                float s0 = scs[lane], s1 = scs[lane + 32];
                float m = fmaxf(s0, s1);
#pragma unroll
                for (int o = 16; o; o >>= 1) m = fmaxf(m, __shfl_xor_sync(0xffffffffu, m, o));
                float e0 = __expf(s0 - m), e1 = __expf(s1 - m);
                float ssum = e0 + e1;
#pragma unroll
                for (int o = 16; o; o >>= 1) ssum += __shfl_xor_sync(0xffffffffu, ssum, o);
                float inv = 1.f / ssum;
                wsf[lane] = e0 * inv;
                wsf[lane + 32] = e1 * inv;
                if (writeAttn) {
                    attn_out[((size_t)b * TD + t) * SS + lane] = e0 * inv;
                    attn_out[((size_t)b * TD + t) * SS + lane + 32] = e1 * inv;
                }
            }
            __syncthreads();
            for (int j = tid; j < 512; j += 256) {
                float a = 0.f;
                const float* ep = g_enc_out + (size_t)b * SS * 512 + j;
#pragma unroll 8
                for (int s = 0; s < SS; s++) a += wsf[s] * ep[(size_t)s * 512];
                __stcg(&g_ctx[j * 128 + b], a);
            }
        }
        gbar(&g_bar_dec, (unsigned)(t * 3 + 2) * NB);

        // ---- phase C: gates = embW + [ctx,h] @ W^T, fused cell ----
        float ew[2][4];
#pragma unroll
        for (int ci = 0; ci < 2; ci++) {
            int idx = tid + ci * 256;
            int u = idx >> 7, b = idx & 127;
            const size_t base = ((size_t)t * BB + b) * 2048 + blk * 4 + u;
            ew[ci][0] = __ldg(&g_embW[base]);
            ew[ci][1] = __ldg(&g_embW[base + 512]);
            ew[ci][2] = __ldg(&g_embW[base + 1024]);
            ew[ci][3] = __ldg(&g_embW[base + 1536]);
        }
        float a0 = 0.f, a1 = 0.f, a2 = 0.f, a3 = 0.f, a4 = 0.f, a5 = 0.f, a6 = 0.f, a7 = 0.f;
        prefetch4(pre, g_ctx);
        commit4(stage, pre);
        __syncthreads();
        for (int c = 0; c < 32; c++) {
            float* st = stage + (c & 1) * 4224;
            if (c < 31) {
                const float* nsrc = (c + 1 < 16) ? (g_ctx + (c + 1) * 4096)
                                                 : (hsrc + (c + 1 - 16) * 4096);
                prefetch4(pre, nsrc);
            }
            const float* wrow = wsC + r16 * 1025 + c * 32;
#pragma unroll
            for (int kk = 0; kk < 32; kk++) {
                float w = wrow[kk];
                const float* hp = st + kk * 132 + (b8 << 3);
                float4 h0 = *(const float4*)hp;
                float4 h1 = *(const float4*)(hp + 4);
                a0 += w * h0.x; a1 += w * h0.y; a2 += w * h0.z; a3 += w * h0.w;
                a4 += w * h1.x; a5 += w * h1.y; a6 += w * h1.z; a7 += w * h1.w;
            }
            __syncthreads();
            if (c < 31) commit4(stage + ((c + 1) & 1) * 4224, pre);
            __syncthreads();
        }
        {
            float* gr = gbufS + r16 * 132 + (b8 << 3);
            gr[0] = a0; gr[1] = a1; gr[2] = a2; gr[3] = a3;
            gr[4] = a4; gr[5] = a5; gr[6] = a6; gr[7] = a7;
        }
        __syncthreads();
#pragma unroll
        for (int ci = 0; ci < 2; ci++) {
            int idx = tid + ci * 256;
            int u = idx >> 7, b = idx & 127;
            float ig = gbufS[u * 132 + b]        + ew[ci][0];
            float fg = gbufS[(4 + u) * 132 + b]  + ew[ci][1];
            float gg = gbufS[(8 + u) * 132 + b]  + ew[ci][2];
            float og = gbufS[(12 + u) * 132 + b] + ew[ci][3];
            float cp = csm[u * 128 + b];
            float cn = sigf(fg) * cp + sigf(ig) * tanhf(gg);
            float hn = sigf(og) * tanhf(cn);
            csm[u * 128 + b] = cn;
            int hr = blk * 4 + u;
            __stcg(&g_hbuf[((t + 1) & 1) * 65536 + hr * 128 + b], hn);
            g_hs[((size_t)t * BB + b) * 512 + hr] = hn;
        }
        gbar(&g_bar_dec, (unsigned)(t * 3 + 3) * NB);
    }
}

// ---------------- generic SGEMM-NT (unchanged from R1) ----------------
__global__ __launch_bounds__(256) void gemm_nt(
    const float* __restrict__ A, int lda, const int* __restrict__ arow,
    const float* __restrict__ B, int ldb, const float* __restrict__ bias,
    float* __restrict__ C, int M, int N, int K, int mode)
{
    __shared__ float As[8][132];
    __shared__ float Bs[8][132];
    const int bn = blockIdx.x * 128;
    const int bm = blockIdx.y * 128;
    const int tid = threadIdx.x;
    const int lr = tid >> 1;
    const int lk = (tid & 1) << 2;
    const int tm = (tid >> 4) << 3;
    const int tn = (tid & 15) << 3;

    const int am = bm + lr;
    const int ar = arow ? arow[am] : am;
    const float* Ap = A + (size_t)ar * lda + lk;
    const int bnr = bn + lr;
    const bool bval = (bnr < N);
    const float* Bp = B + (size_t)(bval ? bnr : 0) * ldb + lk;

    float acc[8][8];
#pragma unroll
    for (int i = 0; i < 8; i++)
#pragma unroll
        for (int j = 0; j < 8; j++) acc[i][j] = 0.f;

    for (int k0 = 0; k0 < K; k0 += 8) {
        float4 av = *(const float4*)(Ap + k0);
        float4 bv = bval ? *(const float4*)(Bp + k0) : make_float4(0.f, 0.f, 0.f, 0.f);
        __syncthreads();
        As[lk + 0][lr] = av.x; As[lk + 1][lr] = av.y; As[lk + 2][lr] = av.z; As[lk + 3][lr] = av.w;
        Bs[lk + 0][lr] = bv.x; Bs[lk + 1][lr] = bv.y; Bs[lk + 2][lr] = bv.z; Bs[lk + 3][lr] = bv.w;
        __syncthreads();
#pragma unroll
        for (int kk = 0; kk < 8; kk++) {
            float a[8], b[8];
            *(float4*)(a)     = *(const float4*)&As[kk][tm];
            *(float4*)(a + 4) = *(const float4*)&As[kk][tm + 4];
            *(float4*)(b)     = *(const float4*)&Bs[kk][tn];
            *(float4*)(b + 4) = *(const float4*)&Bs[kk][tn + 4];
#pragma unroll
            for (int i = 0; i < 8; i++)
#pragma unroll
                for (int j = 0; j < 8; j++)
                    acc[i][j] += a[i] * b[j];
        }
    }
#pragma unroll
    for (int i = 0; i < 8; i++) {
        const int m = bm + tm + i;
#pragma unroll
        for (int j = 0; j < 8; j++) {
            const int n = bn + tn + j;
            if (n < N) {
                float v = acc[i][j] + (bias ? bias[n] : 0.f);
                size_t off;
                if (mode == 1) off = (size_t)((m & 127) * TD + (m >> 7)) * N + n;
                else           off = (size_t)m * N + n;
                C[off] = v;
            }
        }
    }
}

// ---------------- small helpers ----------------
__global__ void zero_init()
{
    int i = blockIdx.x * 256 + threadIdx.x;   // grid 512 -> 131072
    g_hbuf[i] = 0.f;
    if (i == 0) { g_bar_enc = 0u; g_bar_dec = 0u; }
}

__global__ void build_rows(const int* __restrict__ tgt)
{
    int i = blockIdx.x * 256 + threadIdx.x;
    if (i < TD * BB) {
        int tt = i >> 7, b = i & 127;
        g_rows[i] = (tt == 0) ? 1 : tgt[b * 33 + tt];
    }
}

// ---------------- launch ----------------
extern "C" void kernel_launch(void* const* d_in, const int* in_sizes, int n_in,
                              void* d_out, int out_size)
{
    (void)in_sizes; (void)n_in;
    const int*   src     = (const int*)d_in[0];
    const int*   tgt     = (const int*)d_in[1];
    const float* enc_emb = (const float*)d_in[2];
    const float* enc_Wih = (const float*)d_in[3];
    const float* enc_Whh = (const float*)d_in[4];
    const float* enc_b   = (const float*)d_in[5];
    const float* dec_emb = (const float*)d_in[6];
    const float* Wq      = (const float*)d_in[7];
    const float* bq      = (const float*)d_in[8];
    const float* Wk      = (const float*)d_in[9];
    const float* bk      = (const float*)d_in[10];
    const float* v_w     = (const float*)d_in[11];
    const float* v_b     = (const float*)d_in[12];
    const float* dWih    = (const float*)d_in[13];
    const float* dWhh    = (const float*)d_in[14];
    const float* db      = (const float*)d_in[15];
    const float* Wo      = (const float*)d_in[16];
    const float* bo      = (const float*)d_in[17];
    float* out = (float*)d_out;

    void *p_xg, *p_enc, *p_keys, *p_embW, *p_hs, *p_rows;
    cudaGetSymbolAddress(&p_xg,   g_xg);
    cudaGetSymbolAddress(&p_enc,  g_enc_out);
    cudaGetSymbolAddress(&p_keys, g_keys);
    cudaGetSymbolAddress(&p_embW, g_embW);
    cudaGetSymbolAddress(&p_hs,   g_hs);
    cudaGetSymbolAddress(&p_rows, g_rows);

    const int ENC_SMEM = 19280 * 4;   // 77120 B
    const int DEC_SMEM = 32740 * 4;   // 130960 B
    cudaFuncSetAttribute(enc_persist, cudaFuncAttributeMaxDynamicSharedMemorySize, ENC_SMEM);
    cudaFuncSetAttribute(dec_persist, cudaFuncAttributeMaxDynamicSharedMemorySize, DEC_SMEM);

    zero_init<<<512, 256>>>();

    // encoder input gates + decoder emb-gates precompute (independent of recurrence)
    gemm_nt<<<dim3(16, 64), 256>>>(enc_emb, 256, src, enc_Wih, 256, enc_b,
                                   (float*)p_xg, 8192, 2048, 256, 0);
    build_rows<<<16, 256>>>(tgt);
    gemm_nt<<<dim3(16, 32), 256>>>(dec_emb, 256, (const int*)p_rows, dWih, 768, db,
                                   (float*)p_embW, 4096, 2048, 256, 0);

    // persistent encoder (64 steps)
    enc_persist<<<NB, 256, ENC_SMEM>>>(enc_Whh);

    // keys_proj = enc_out @ Wk.T + bk
    gemm_nt<<<dim3(4, 64), 256>>>((const float*)p_enc, 512, nullptr, Wk, 512, bk,
                                  (float*)p_keys, 8192, 512, 512, 0);

    const long long LOGITS = (long long)BB * TD * VV;
    const long long TOTAL  = LOGITS + (long long)BB * TD * SS;
    int writeAttn = ((long long)out_size >= TOTAL);
    float* attn = out + LOGITS;

    // persistent decoder (32 steps: q -> attention -> gates)
    dec_persist<<<NB, 256, DEC_SMEM>>>(Wq, bq, v_w, v_b, src, dWih, dWhh, attn, writeAttn);

    // logits = hs @ Wo.T + bo
    gemm_nt<<<dim3(157, 32), 256>>>((const float*)p_hs, 512, nullptr, Wo, 512, bo,
                                    out, 4096, 20000, 512, 1);
}

// round 4
// speedup vs baseline: 1.0114x; 1.0114x over previous
#include <cuda_runtime.h>
#include <math.h>

#define VV 20000
#define HH 512
#define BB 128
#define SS 64
#define TD 32

// ---------------- scratch (device globals) ----------------
__device__ float g_xg[BB * SS * 2048];
__device__ float g_enc_out[BB * SS * HH];
__device__ float g_keys[BB * SS * HH];
__device__ float g_embW[TD * BB * 2048];
__device__ float g_hs[TD * BB * HH];
__device__ float g_h0[BB * HH];
__device__ float g_h1[BB * HH];
__device__ float g_c[BB * HH];
__device__ float g_q[BB * HH];
__device__ float g_ctx[BB * HH];
__device__ int   g_rows[TD * BB];

__device__ __forceinline__ float sigf(float x) { return 1.f / (1.f + __expf(-x)); }
__device__ __forceinline__ float tanha(float x) {
    float y; asm("tanh.approx.f32 %0, %1;" : "=f"(y) : "f"(x)); return y;
}
__device__ __forceinline__ float to_tf32(float x) {
    float y; asm("cvt.rna.tf32.f32 %0, %1;" : "=f"(y) : "f"(x)); return y;
}

// ================= TF32 MMA logits GEMM =================
// C = remap( A[4096,512] @ B[20000,512]^T + bias ),  row m=t*128+b -> out row b*TD+t
#define LST 136
__global__ __launch_bounds__(256) void gemm_tf32_logits(
    const float* __restrict__ A, const float* __restrict__ B,
    const float* __restrict__ bias, float* __restrict__ C)
{
    __shared__ float As[2][16][LST];
    __shared__ float Bs[2][16][LST];
    const int bm = blockIdx.y * 128;
    const int bn = blockIdx.x * 128;
    const int tid = threadIdx.x;
    const int warp = tid >> 5, lane = tid & 31;
    const int wm = (warp >> 2) * 64, wn = (warp & 3) * 32;
    const int g = lane >> 2, tg = lane & 3;

    const int lr = tid & 127;           // tile row (m or n)
    const int lc = tid >> 7;            // 0/1 -> k cols lc*4.. and lc*4+8..
    const float* Ap = A + (size_t)(bm + lr) * 512 + lc * 4;
    const int bnr = bn + lr;
    const bool bok = (bnr < VV);
    const float* Bp = B + (size_t)(bok ? bnr : 0) * 512 + lc * 4;

    float acc[4][4][4];
#pragma unroll
    for (int mt = 0; mt < 4; mt++)
#pragma unroll
        for (int nt = 0; nt < 4; nt++)
#pragma unroll
            for (int i = 0; i < 4; i++) acc[mt][nt][i] = 0.f;

    float4 av0 = *(const float4*)(Ap);
    float4 av1 = *(const float4*)(Ap + 8);
    float4 bv0 = bok ? *(const float4*)(Bp)     : make_float4(0.f,0.f,0.f,0.f);
    float4 bv1 = bok ? *(const float4*)(Bp + 8) : make_float4(0.f,0.f,0.f,0.f);

#define STORE_T(buf) do { \
    As[buf][lc*4+0][lr]=to_tf32(av0.x); As[buf][lc*4+1][lr]=to_tf32(av0.y); \
    As[buf][lc*4+2][lr]=to_tf32(av0.z); As[buf][lc*4+3][lr]=to_tf32(av0.w); \
    As[buf][lc*4+8][lr]=to_tf32(av1.x); As[buf][lc*4+9][lr]=to_tf32(av1.y); \
    As[buf][lc*4+10][lr]=to_tf32(av1.z); As[buf][lc*4+11][lr]=to_tf32(av1.w); \
    Bs[buf][lc*4+0][lr]=to_tf32(bv0.x); Bs[buf][lc*4+1][lr]=to_tf32(bv0.y); \
    Bs[buf][lc*4+2][lr]=to_tf32(bv0.z); Bs[buf][lc*4+3][lr]=to_tf32(bv0.w); \
    Bs[buf][lc*4+8][lr]=to_tf32(bv1.x); Bs[buf][lc*4+9][lr]=to_tf32(bv1.y); \
    Bs[buf][lc*4+10][lr]=to_tf32(bv1.z); Bs[buf][lc*4+11][lr]=to_tf32(bv1.w); \
} while(0)

    STORE_T(0);
    __syncthreads();

    for (int kb = 0; kb < 32; kb++) {
        const int cur = kb & 1;
        if (kb < 31) {
            const float* Ap2 = Ap + (kb + 1) * 16;
            const float* Bp2 = Bp + (kb + 1) * 16;
            av0 = *(const float4*)(Ap2);
            av1 = *(const float4*)(Ap2 + 8);
            bv0 = bok ? *(const float4*)(Bp2)     : make_float4(0.f,0.f,0.f,0.f);
            bv1 = bok ? *(const float4*)(Bp2 + 8) : make_float4(0.f,0.f,0.f,0.f);
        }
#pragma unroll
        for (int ks = 0; ks < 2; ks++) {
            const int k = ks * 8;
            unsigned afr[4][4], bfr[4][2];
#pragma unroll
            for (int mt = 0; mt < 4; mt++) {
                const int m = wm + mt * 16 + g;
                afr[mt][0] = __float_as_uint(As[cur][k + tg][m]);
                afr[mt][1] = __float_as_uint(As[cur][k + tg][m + 8]);
                afr[mt][2] = __float_as_uint(As[cur][k + tg + 4][m]);
                afr[mt][3] = __float_as_uint(As[cur][k + tg + 4][m + 8]);
            }
#pragma unroll
            for (int nt = 0; nt < 4; nt++) {
                const int n = wn + nt * 8 + g;
                bfr[nt][0] = __float_as_uint(Bs[cur][k + tg][n]);
                bfr[nt][1] = __float_as_uint(Bs[cur][k + tg + 4][n]);
            }
#pragma unroll
            for (int mt = 0; mt < 4; mt++)
#pragma unroll
                for (int nt = 0; nt < 4; nt++) {
                    asm volatile(
                        "mma.sync.aligned.m16n8k8.row.col.f32.tf32.tf32.f32 "
                        "{%0,%1,%2,%3}, {%4,%5,%6,%7}, {%8,%9}, {%0,%1,%2,%3};"
                        : "+f"(acc[mt][nt][0]), "+f"(acc[mt][nt][1]),
                          "+f"(acc[mt][nt][2]), "+f"(acc[mt][nt][3])
                        : "r"(afr[mt][0]), "r"(afr[mt][1]), "r"(afr[mt][2]), "r"(afr[mt][3]),
                          "r"(bfr[nt][0]), "r"(bfr[nt][1]));
                }
        }
        __syncthreads();
        if (kb < 31) {
            STORE_T(cur ^ 1);
            __syncthreads();
        }
    }

#pragma unroll
    for (int mt = 0; mt < 4; mt++) {
        const int m0 = bm + wm + mt * 16 + g;
        const int r0 = (m0 & 127) * TD + (m0 >> 7);
        const int m1 = m0 + 8;
        const int r1 = (m1 & 127) * TD + (m1 >> 7);
#pragma unroll
        for (int nt = 0; nt < 4; nt++) {
            const int n0 = bn + wn + nt * 8 + 2 * tg;
            if (n0 < VV) {
                const float bv_0 = bias[n0], bv_1 = bias[n0 + 1];
                C[(size_t)r0 * VV + n0]     = acc[mt][nt][0] + bv_0;
                C[(size_t)r0 * VV + n0 + 1] = acc[mt][nt][1] + bv_1;
                C[(size_t)r1 * VV + n0]     = acc[mt][nt][2] + bv_0;
                C[(size_t)r1 * VV + n0 + 1] = acc[mt][nt][3] + bv_1;
            }
        }
    }
}

// ---------------- generic SGEMM-NT (R1) ----------------
__global__ __launch_bounds__(256) void gemm_nt(
    const float* __restrict__ A, int lda, const int* __restrict__ arow,
    const float* __restrict__ B, int ldb, const float* __restrict__ bias,
    float* __restrict__ C, int M, int N, int K, int mode)
{
    __shared__ float As[8][132];
    __shared__ float Bs[8][132];
    const int bn = blockIdx.x * 128;
    const int bm = blockIdx.y * 128;
    const int tid = threadIdx.x;
    const int lr = tid >> 1;
    const int lk = (tid & 1) << 2;
    const int tm = (tid >> 4) << 3;
    const int tn = (tid & 15) << 3;

    const int am = bm + lr;
    const int ar = arow ? arow[am] : am;
    const float* Ap = A + (size_t)ar * lda + lk;
    const int bnr = bn + lr;
    const bool bval = (bnr < N);
    const float* Bp = B + (size_t)(bval ? bnr : 0) * ldb + lk;

    float acc[8][8];
#pragma unroll
    for (int i = 0; i < 8; i++)
#pragma unroll
        for (int j = 0; j < 8; j++) acc[i][j] = 0.f;

    for (int k0 = 0; k0 < K; k0 += 8) {
        float4 av = *(const float4*)(Ap + k0);
        float4 bv = bval ? *(const float4*)(Bp + k0) : make_float4(0.f, 0.f, 0.f, 0.f);
        __syncthreads();
        As[lk + 0][lr] = av.x; As[lk + 1][lr] = av.y; As[lk + 2][lr] = av.z; As[lk + 3][lr] = av.w;
        Bs[lk + 0][lr] = bv.x; Bs[lk + 1][lr] = bv.y; Bs[lk + 2][lr] = bv.z; Bs[lk + 3][lr] = bv.w;
        __syncthreads();
#pragma unroll
        for (int kk = 0; kk < 8; kk++) {
            float a[8], b[8];
            *(float4*)(a)     = *(const float4*)&As[kk][tm];
            *(float4*)(a + 4) = *(const float4*)&As[kk][tm + 4];
            *(float4*)(b)     = *(const float4*)&Bs[kk][tn];
            *(float4*)(b + 4) = *(const float4*)&Bs[kk][tn + 4];
#pragma unroll
            for (int i = 0; i < 8; i++)
#pragma unroll
                for (int j = 0; j < 8; j++)
                    acc[i][j] += a[i] * b[j];
        }
    }
#pragma unroll
    for (int i = 0; i < 8; i++) {
        const int m = bm + tm + i;
#pragma unroll
        for (int j = 0; j < 8; j++) {
            const int n = bn + tn + j;
            if (n < N) {
                float v = acc[i][j] + (bias ? bias[n] : 0.f);
                C[(size_t)m * N + n] = v;
            }
        }
    }
}

// ---------------- encoder step v2: grid (32,4), 128 threads ----------------
// block: 16 hidden units (j0=bx*16), 32 batches (b0=by*32), 4 gates.
__global__ __launch_bounds__(128) void enc_step(const float* __restrict__ Whh, int t)
{
    __shared__ float hs[32][34];       // [kk][b]
    __shared__ float ws[4][32][18];    // [g][kk][jj]
    const int tid = threadIdx.x;
    const int tj = tid & 7;            // 8 x 2 = 16 j
    const int tb = tid >> 3;           // 16 x 2 = 32 b
    const int j0 = blockIdx.x * 16;
    const int b0 = blockIdx.y * 32;
    const float* hin = (t & 1) ? g_h1 : g_h0;
    float* hout      = (t & 1) ? g_h0 : g_h1;

    float acc[4][2][2];
#pragma unroll
    for (int g = 0; g < 4; g++) { acc[g][0][0] = acc[g][0][1] = acc[g][1][0] = acc[g][1][1] = 0.f; }

    for (int k0 = 0; k0 < 512; k0 += 32) {
        __syncthreads();
#pragma unroll
        for (int i = 0; i < 8; i++) {
            int idx = i * 128 + tid;
            int bb = idx >> 5, kk = idx & 31;
            hs[kk][bb] = hin[(size_t)(b0 + bb) * 512 + k0 + kk];
        }
#pragma unroll
        for (int i = 0; i < 16; i++) {
            int idx = i * 128 + tid;
            int g = idx >> 9, jj = (idx >> 5) & 15, kk = idx & 31;
            ws[g][kk][jj] = Whh[(size_t)((g << 9) + j0 + jj) * 512 + k0 + kk];
        }
        __syncthreads();
#pragma unroll
        for (int kk = 0; kk < 32; kk++) {
            float2 hp = *(const float2*)&hs[kk][tb * 2];
#pragma unroll
            for (int g = 0; g < 4; g++) {
                float2 wp = *(const float2*)&ws[g][kk][tj * 2];
                acc[g][0][0] += hp.x * wp.x;
                acc[g][0][1] += hp.x * wp.y;
                acc[g][1][0] += hp.y * wp.x;
                acc[g][1][1] += hp.y * wp.y;
            }
        }
    }
#pragma unroll
    for (int bi = 0; bi < 2; bi++)
#pragma unroll
        for (int ji = 0; ji < 2; ji++) {
            const int b = b0 + tb * 2 + bi;
            const int j = j0 + tj * 2 + ji;
            const size_t xb = ((size_t)b * SS + t) * 2048 + j;
            float ig = acc[0][bi][ji] + g_xg[xb];
            float fg = acc[1][bi][ji] + g_xg[xb + 512];
            float gg = acc[2][bi][ji] + g_xg[xb + 1024];
            float og = acc[3][bi][ji] + g_xg[xb + 1536];
            float cp = g_c[b * 512 + j];
            float cn = sigf(fg) * cp + sigf(ig) * tanhf(gg);
            float hn = sigf(og) * tanhf(cn);
            g_c[b * 512 + j] = cn;
            hout[b * 512 + j] = hn;
            g_enc_out[((size_t)b * SS + t) * 512 + j] = hn;
        }
}

// ---------------- decoder step v2: grid (32,4), 128 threads ----------------
__global__ __launch_bounds__(128) void dec_step(const float* __restrict__ dWih,
                                                const float* __restrict__ dWhh, int t)
{
    __shared__ float hs[32][34];
    __shared__ float ws[4][32][18];
    const int tid = threadIdx.x;
    const int tj = tid & 7;
    const int tb = tid >> 3;
    const int j0 = blockIdx.x * 16;
    const int b0 = blockIdx.y * 32;
    const float* hin = (t & 1) ? g_h1 : g_h0;
    float* hout      = (t & 1) ? g_h0 : g_h1;

    float acc[4][2][2];
#pragma unroll
    for (int g = 0; g < 4; g++) { acc[g][0][0] = acc[g][0][1] = acc[g][1][0] = acc[g][1][1] = 0.f; }

    for (int k0 = 0; k0 < 1024; k0 += 32) {
        const bool isCtx = (k0 < 512);
        __syncthreads();
#pragma unroll
        for (int i = 0; i < 8; i++) {
            int idx = i * 128 + tid;
            int bb = idx >> 5, kk = idx & 31;
            int kg = k0 + kk;
            hs[kk][bb] = isCtx ? g_ctx[(size_t)(b0 + bb) * 512 + kg]
                               : hin[(size_t)(b0 + bb) * 512 + kg - 512];
        }
#pragma unroll
        for (int i = 0; i < 16; i++) {
            int idx = i * 128 + tid;
            int g = idx >> 9, jj = (idx >> 5) & 15, kk = idx & 31;
            int kg = k0 + kk;
            int n = (g << 9) + j0 + jj;
            ws[g][kk][jj] = isCtx ? dWih[(size_t)n * 768 + 256 + kg]
                                  : dWhh[(size_t)n * 512 + kg - 512];
        }
        __syncthreads();
#pragma unroll
        for (int kk = 0; kk < 32; kk++) {
            float2 hp = *(const float2*)&hs[kk][tb * 2];
#pragma unroll
            for (int g = 0; g < 4; g++) {
                float2 wp = *(const float2*)&ws[g][kk][tj * 2];
                acc[g][0][0] += hp.x * wp.x;
                acc[g][0][1] += hp.x * wp.y;
                acc[g][1][0] += hp.y * wp.x;
                acc[g][1][1] += hp.y * wp.y;
            }
        }
    }
#pragma unroll
    for (int bi = 0; bi < 2; bi++)
#pragma unroll
        for (int ji = 0; ji < 2; ji++) {
            const int b = b0 + tb * 2 + bi;
            const int j = j0 + tj * 2 + ji;
            const size_t mb = ((size_t)t * BB + b) * 2048 + j;
            float ig = acc[0][bi][ji] + g_embW[mb];
            float fg = acc[1][bi][ji] + g_embW[mb + 512];
            float gg = acc[2][bi][ji] + g_embW[mb + 1024];
            float og = acc[3][bi][ji] + g_embW[mb + 1536];
            float cp = g_c[b * 512 + j];
            float cn = sigf(fg) * cp + sigf(ig) * tanhf(gg);
            float hn = sigf(og) * tanhf(cn);
            g_c[b * 512 + j] = cn;
            hout[b * 512 + j] = hn;
            g_hs[((size_t)t * BB + b) * 512 + j] = hn;
        }
}

// ---------------- q = h@Wq.T + bq, grid (32,4), 128 threads ----------------
__global__ __launch_bounds__(128) void q_step(const float* __restrict__ Wq,
                                              const float* __restrict__ bq, int t)
{
    __shared__ float hs[32][34];
    __shared__ float ws[32][18];
    const int tid = threadIdx.x;
    const int tj = tid & 7;
    const int tb = tid >> 3;
    const int j0 = blockIdx.x * 16;
    const int b0 = blockIdx.y * 32;
    const float* hin = (t & 1) ? g_h1 : g_h0;

    float acc[2][2] = {{0.f, 0.f}, {0.f, 0.f}};
    for (int k0 = 0; k0 < 512; k0 += 32) {
        __syncthreads();
#pragma unroll
        for (int i = 0; i < 8; i++) {
            int idx = i * 128 + tid;
            int bb = idx >> 5, kk = idx & 31;
            hs[kk][bb] = hin[(size_t)(b0 + bb) * 512 + k0 + kk];
        }
#pragma unroll
        for (int i = 0; i < 4; i++) {
            int idx = i * 128 + tid;
            int jj = idx >> 5, kk = idx & 31;
            ws[kk][jj] = Wq[(size_t)(j0 + jj) * 512 + k0 + kk];
        }
        __syncthreads();
#pragma unroll
        for (int kk = 0; kk < 32; kk++) {
            float2 hp = *(const float2*)&hs[kk][tb * 2];
            float2 wp = *(const float2*)&ws[kk][tj * 2];
            acc[0][0] += hp.x * wp.x;
            acc[0][1] += hp.x * wp.y;
            acc[1][0] += hp.y * wp.x;
            acc[1][1] += hp.y * wp.y;
        }
    }
#pragma unroll
    for (int bi = 0; bi < 2; bi++)
#pragma unroll
        for (int ji = 0; ji < 2; ji++) {
            const int b = b0 + tb * 2 + bi;
            const int j = j0 + tj * 2 + ji;
            g_q[b * 512 + j] = acc[bi][ji] + bq[j];
        }
}

// ---------------- attention (block per batch element) ----------------
__global__ __launch_bounds__(256) void att_step(const float* __restrict__ v_w,
                                                const float* __restrict__ v_b,
                                                const int* __restrict__ src,
                                                float* __restrict__ attn_out,
                                                int t, int writeAttn)
{
    const int b = blockIdx.x;
    const int tid = threadIdx.x;
    __shared__ float qs[512], vs[512], sc[64];
    qs[tid] = g_q[b * 512 + tid];
    qs[tid + 256] = g_q[b * 512 + tid + 256];
    vs[tid] = v_w[tid];
    vs[tid + 256] = v_w[tid + 256];
    __syncthreads();
    const int warp = tid >> 5, lane = tid & 31;
    for (int s = warp; s < 64; s += 8) {
        const float* kp = g_keys + ((size_t)b * SS + s) * 512;
        float sum = 0.f;
#pragma unroll 4
        for (int j = lane; j < 512; j += 32)
            sum += tanha(qs[j] + kp[j]) * vs[j];
#pragma unroll
        for (int o = 16; o; o >>= 1) sum += __shfl_xor_sync(0xffffffffu, sum, o);
        if (lane == 0) {
            sum += v_b[0];
            if (src[b * SS + s] == 0) sum = -1e9f;
            sc[s] = sum;
        }
    }
    __syncthreads();
    if (warp == 0) {
        float a0 = sc[lane], a1 = sc[lane + 32];
        float m = fmaxf(a0, a1);
#pragma unroll
        for (int o = 16; o; o >>= 1) m = fmaxf(m, __shfl_xor_sync(0xffffffffu, m, o));
        float e0 = __expf(a0 - m), e1 = __expf(a1 - m);
        float ss = e0 + e1;
#pragma unroll
        for (int o = 16; o; o >>= 1) ss += __shfl_xor_sync(0xffffffffu, ss, o);
        float inv = 1.f / ss;
        sc[lane] = e0 * inv;
        sc[lane + 32] = e1 * inv;
        if (writeAttn) {
            attn_out[((size_t)b * TD + t) * SS + lane] = e0 * inv;
            attn_out[((size_t)b * TD + t) * SS + lane + 32] = e1 * inv;
        }
    }
    __syncthreads();
    for (int j = tid; j < 512; j += 256) {
        float a = 0.f;
        const float* ep = g_enc_out + (size_t)b * SS * 512 + j;
#pragma unroll 8
        for (int s = 0; s < 64; s++) a += sc[s] * ep[(size_t)s * 512];
        g_ctx[b * 512 + j] = a;
    }
}

// ---------------- small helpers ----------------
__global__ void zero_hc()
{
    int i = blockIdx.x * 256 + threadIdx.x;   // grid 256 -> 65536
    g_h0[i] = 0.f;
    g_c[i] = 0.f;
}

__global__ void build_rows(const int* __restrict__ tgt)
{
    int i = blockIdx.x * 256 + threadIdx.x;
    if (i < TD * BB) {
        int tt = i >> 7, b = i & 127;
        g_rows[i] = (tt == 0) ? 1 : tgt[b * 33 + tt];
    }
}

// ---------------- launch ----------------
extern "C" void kernel_launch(void* const* d_in, const int* in_sizes, int n_in,
                              void* d_out, int out_size)
{
    (void)in_sizes; (void)n_in;
    const int*   src     = (const int*)d_in[0];
    const int*   tgt     = (const int*)d_in[1];
    const float* enc_emb = (const float*)d_in[2];
    const float* enc_Wih = (const float*)d_in[3];
    const float* enc_Whh = (const float*)d_in[4];
    const float* enc_b   = (const float*)d_in[5];
    const float* dec_emb = (const float*)d_in[6];
    const float* Wq      = (const float*)d_in[7];
    const float* bq      = (const float*)d_in[8];
    const float* Wk      = (const float*)d_in[9];
    const float* bk      = (const float*)d_in[10];
    const float* v_w     = (const float*)d_in[11];
    const float* v_b     = (const float*)d_in[12];
    const float* dWih    = (const float*)d_in[13];
    const float* dWhh    = (const float*)d_in[14];
    const float* db      = (const float*)d_in[15];
    const float* Wo      = (const float*)d_in[16];
    const float* bo      = (const float*)d_in[17];
    float* out = (float*)d_out;

    void *p_xg, *p_enc, *p_keys, *p_embW, *p_hs, *p_rows;
    cudaGetSymbolAddress(&p_xg,   g_xg);
    cudaGetSymbolAddress(&p_enc,  g_enc_out);
    cudaGetSymbolAddress(&p_keys, g_keys);
    cudaGetSymbolAddress(&p_embW, g_embW);
    cudaGetSymbolAddress(&p_hs,   g_hs);
    cudaGetSymbolAddress(&p_rows, g_rows);

    zero_hc<<<256, 256>>>();

    // encoder input gates: [8192,2048] = emb[src] @ enc_Wih.T + enc_b
    gemm_nt<<<dim3(16, 64), 256>>>(enc_emb, 256, src, enc_Wih, 256, enc_b,
                                   (float*)p_xg, 8192, 2048, 256, 0);

    // decoder embedding rows + precomputed emb@Wih[:, :E].T + dec_b
    build_rows<<<16, 256>>>(tgt);
    gemm_nt<<<dim3(16, 32), 256>>>(dec_emb, 256, (const int*)p_rows, dWih, 768, db,
                                   (float*)p_embW, 4096, 2048, 256, 0);

    // encoder recurrence
    for (int t = 0; t < SS; t++)
        enc_step<<<dim3(32, 4), 128>>>(enc_Whh, t);

    // keys_proj = enc_out @ Wk.T + bk
    gemm_nt<<<dim3(4, 64), 256>>>((const float*)p_enc, 512, nullptr, Wk, 512, bk,
                                  (float*)p_keys, 8192, 512, 512, 0);

    const long long LOGITS = (long long)BB * TD * VV;
    const long long TOTAL  = LOGITS + (long long)BB * TD * SS;
    int writeAttn = ((long long)out_size >= TOTAL);
    float* attn = out + LOGITS;

    // decoder recurrence
    for (int t = 0; t < TD; t++) {
        q_step<<<dim3(32, 4), 128>>>(Wq, bq, t);
        att_step<<<128, 256>>>(v_w, v_b, src, attn, t, writeAttn);
        dec_step<<<dim3(32, 4), 128>>>(dWih, dWhh, t);
    }

    // logits = hs @ Wo.T + bo  via TF32 tensor cores
    gemm_tf32_logits<<<dim3(157, 32), 256>>>((const float*)p_hs, Wo, bo, out);
}